// round 7
// baseline (speedup 1.0000x reference)
#include <cuda_runtime.h>
#include <cstdint>
#include <math.h>

#define NTOK 8192
#define DIM  1024
#define HID  256
#define HIDC 128
#define POOL 16384
#define TOPK 1024

// ---------------- scratch (device globals: no allocations allowed) ----------
__device__ float g_hs[NTOK * HID];                              // 8 MB
__device__ float g_hc[NTOK * HIDC];                             // 4 MB
__device__ float g_scores[(size_t)NTOK * POOL];                 // 512 MB
__device__ unsigned long long g_pairs[(size_t)NTOK * 2048];     // 128 MB
__device__ int   g_budget[NTOK];

// packed fp32x2 FMA (sm_100+): two independent rn-rounded fp32 FMAs per issue.
__device__ __forceinline__ float2 ffma2(float2 a, float2 b, float2 c) {
    unsigned long long A = *(unsigned long long*)&a;
    unsigned long long B = *(unsigned long long*)&b;
    unsigned long long C = *(unsigned long long*)&c;
    unsigned long long D;
    asm("fma.rn.f32x2 %0, %1, %2, %3;" : "=l"(D) : "l"(A), "l"(B), "l"(C));
    return *(float2*)&D;
}

// ---------------- fp32x2 GEMM core (proven R2 version), as device func ------
template<bool RELU>
__device__ __forceinline__ void gemm_body(const float* __restrict__ A,
                                          const float* __restrict__ B,
                                          const float* __restrict__ bias,
                                          float* __restrict__ C,
                                          int N, int K, int bm, int bn,
                                          float Asm[2][8][128], float Bsm[2][8][128])
{
    const int tid = threadIdx.x;
    const int tx  = tid & 15;
    const int ty  = tid >> 4;

    float2 acc[8][4];
#pragma unroll
    for (int i = 0; i < 8; i++)
#pragma unroll
        for (int q = 0; q < 4; q++) acc[i][q] = make_float2(0.f, 0.f);

    const int ar = tid >> 1;
    const int ac = (tid & 1) * 4;
    const int br = tid >> 5;
    const int bc = (tid & 31) * 4;
    const float* Aptr = A + (size_t)(bm + ar) * K + ac;
    const float* Bptr = B + (size_t)br * N + bn + bc;

    const int NT = K >> 3;

    float4 av = *(const float4*)(Aptr);
    float4 bv = *(const float4*)(Bptr);
    Asm[0][ac + 0][ar] = av.x; Asm[0][ac + 1][ar] = av.y;
    Asm[0][ac + 2][ar] = av.z; Asm[0][ac + 3][ar] = av.w;
    *(float4*)&Bsm[0][br][bc] = bv;
    __syncthreads();

    for (int t = 0; t < NT; t++) {
        const int buf = t & 1;
        const bool more = (t + 1) < NT;
        if (more) {
            av = *(const float4*)(Aptr + (t + 1) * 8);
            bv = *(const float4*)(Bptr + (size_t)(t + 1) * 8 * N);
        }

#pragma unroll
        for (int k = 0; k < 8; k++) {
            float4 a0 = *(const float4*)&Asm[buf][k][ty * 8];
            float4 a1 = *(const float4*)&Asm[buf][k][ty * 8 + 4];
            float4 b0 = *(const float4*)&Bsm[buf][k][tx * 4];
            float4 b1 = *(const float4*)&Bsm[buf][k][tx * 4 + 64];
            float2 bp[4];
            bp[0] = make_float2(b0.x, b0.y); bp[1] = make_float2(b0.z, b0.w);
            bp[2] = make_float2(b1.x, b1.y); bp[3] = make_float2(b1.z, b1.w);
            float a[8] = {a0.x, a0.y, a0.z, a0.w, a1.x, a1.y, a1.z, a1.w};
#pragma unroll
            for (int i = 0; i < 8; i++) {
                float2 ad = make_float2(a[i], a[i]);
#pragma unroll
                for (int q = 0; q < 4; q++)
                    acc[i][q] = ffma2(ad, bp[q], acc[i][q]);
            }
        }

        if (more) {
            const int nb = buf ^ 1;
            Asm[nb][ac + 0][ar] = av.x; Asm[nb][ac + 1][ar] = av.y;
            Asm[nb][ac + 2][ar] = av.z; Asm[nb][ac + 3][ar] = av.w;
            *(float4*)&Bsm[nb][br][bc] = bv;
        }
        __syncthreads();
    }

#pragma unroll
    for (int i = 0; i < 8; i++) {
        const int row = bm + ty * 8 + i;
#pragma unroll
        for (int g = 0; g < 2; g++) {
            const int col = bn + tx * 4 + g * 64;
            float4 v;
            v.x = acc[i][g * 2 + 0].x + bias[col + 0];
            v.y = acc[i][g * 2 + 0].y + bias[col + 1];
            v.z = acc[i][g * 2 + 1].x + bias[col + 2];
            v.w = acc[i][g * 2 + 1].y + bias[col + 3];
            if (RELU) {
                v.x = fmaxf(v.x, 0.f); v.y = fmaxf(v.y, 0.f);
                v.z = fmaxf(v.z, 0.f); v.w = fmaxf(v.w, 0.f);
            }
            *(float4*)(C + (size_t)row * N + col) = v;
        }
    }
}

// GEMM2: scores = hs @ ws2 + bs2 (no relu)
__global__ void __launch_bounds__(256, 2)
sgemm2_bias(const float* __restrict__ A, const float* __restrict__ B,
            const float* __restrict__ bias, float* __restrict__ C,
            int N, int K)
{
    __shared__ float As[2][8][128];
    __shared__ float Bs[2][8][128];
    gemm_body<false>(A, B, bias, C, N, K, blockIdx.y * 128, blockIdx.x * 128, As, Bs);
}

// fused small GEMMs: bx<2 -> hs tile (N=256), bx==2 -> hc tile (N=128)
__global__ void __launch_bounds__(256, 2)
small_gemms(const float* __restrict__ x,
            const float* __restrict__ ws1, const float* __restrict__ bs1,
            const float* __restrict__ w1c, const float* __restrict__ b1c,
            float* __restrict__ hs, float* __restrict__ hc)
{
    __shared__ float As[2][8][128];
    __shared__ float Bs[2][8][128];
    const int bx = blockIdx.x;
    if (bx < 2)
        gemm_body<true>(x, ws1, bs1, hs, HID,  DIM, blockIdx.y * 128, bx * 128, As, Bs);
    else
        gemm_body<true>(x, w1c, b1c, hc, HIDC, DIM, blockIdx.y * 128, 0, As, Bs);
}

// ---------------- complexity -> sigmoid -> budget ---------------------------
__global__ void complexity_kernel(const float* __restrict__ hc,
                                  const float* __restrict__ w2c,
                                  const float* __restrict__ b2c,
                                  float* __restrict__ out_c,
                                  int* __restrict__ budget)
{
    int warp = (blockIdx.x * blockDim.x + threadIdx.x) >> 5;
    int lane = threadIdx.x & 31;
    if (warp >= NTOK) return;
    const float* h = hc + (size_t)warp * HIDC;
    float s = 0.f;
#pragma unroll
    for (int i = lane; i < HIDC; i += 32) s += h[i] * w2c[i];
#pragma unroll
    for (int o = 16; o; o >>= 1) s += __shfl_xor_sync(0xFFFFFFFFu, s, o);
    if (lane == 0) {
        float z = s + b2c[0];
        float c = 1.f / (1.f + expf(-z));
        out_c[warp] = c;
        float raw = 100.f + 924.f * (c * c);
        raw = fminf(fmaxf(raw, 100.f), 1024.f);
        budget[warp] = (int)rintf(raw);
    }
}

// ---------------- top-k helpers ---------------------------------------------
__device__ __forceinline__ uint32_t f2mk(float f) {
    uint32_t u = __float_as_uint(f);
    return (u & 0x80000000u) ? ~u : (u | 0x80000000u);
}
__device__ __forceinline__ float mk2f(uint32_t mk) {
    uint32_t u = (mk & 0x80000000u) ? (mk ^ 0x80000000u) : ~mk;
    return __uint_as_float(u);
}
__device__ __forceinline__ int swz(int i) { return i ^ ((i >> 4) & 15); }

__device__ __forceinline__ void cmpsel(unsigned long long& a, unsigned long long b,
                                       bool want_max) {
    bool take = want_max ? (b > a) : (b < a);
    if (take) a = b;
}
__device__ __forceinline__ void shfl_stage(unsigned long long v[4], int lanexor,
                                           bool desc, int t) {
    const bool wm = (((t & lanexor) == 0) == desc);
#pragma unroll
    for (int e = 0; e < 4; e++) {
        unsigned long long o = __shfl_xor_sync(0xFFFFFFFFu, v[e], lanexor);
        cmpsel(v[e], o, wm);
    }
}
__device__ __forceinline__ void local_j2(unsigned long long v[4], bool desc) {
    unsigned long long a0 = v[0], a2 = v[2];
    cmpsel(v[0], a2, desc);  cmpsel(v[2], a0, !desc);
    unsigned long long a1 = v[1], a3 = v[3];
    cmpsel(v[1], a3, desc);  cmpsel(v[3], a1, !desc);
}
__device__ __forceinline__ void local_j1(unsigned long long v[4], bool d0, bool d1) {
    unsigned long long a = v[0], b = v[1];
    cmpsel(v[0], b, d0);  cmpsel(v[1], a, !d0);
    unsigned long long c = v[2], d = v[3];
    cmpsel(v[2], d, d1);  cmpsel(v[3], c, !d1);
}
__device__ __forceinline__ void merge128(unsigned long long v[4], bool desc, int t) {
    shfl_stage(v, 16, desc, t);
    shfl_stage(v,  8, desc, t);
    shfl_stage(v,  4, desc, t);
    shfl_stage(v,  2, desc, t);
    shfl_stage(v,  1, desc, t);
    local_j2(v, desc);
    local_j1(v, desc, desc);
}
__device__ __forceinline__ void smem_stage(unsigned long long* sp,
                                           unsigned long long v[4],
                                           int j, bool desc, int t) {
#pragma unroll
    for (int e = 0; e < 4; e++) sp[swz(4 * t + e)] = v[e];
    __syncthreads();
    const bool wm = (((t & (j >> 2)) == 0) == desc);
#pragma unroll
    for (int e = 0; e < 4; e++) {
        unsigned long long o = sp[swz((4 * t + e) ^ j)];
        cmpsel(v[e], o, wm);
    }
    __syncthreads();
}

// ---------------- kernel S: threshold-select survivors to global ------------
__global__ void __launch_bounds__(1024)
select_kernel(const float* __restrict__ scores,
              unsigned long long* __restrict__ gpairs)
{
    __shared__ uint32_t hist[4096];
    __shared__ uint32_t chunksum[256];
    __shared__ uint32_t s_bstar, s_cnt;

    const int t    = blockIdx.x;
    const int tid  = threadIdx.x;
    const int lane = tid & 31;
    const uint32_t lt_mask = (1u << lane) - 1u;
    const float4* row4 = (const float4*)(scores + (size_t)t * POOL);
    unsigned long long* gp = gpairs + (size_t)t * 2048;

    uint32_t cnt = 0;
    bool     use_sample = true;
    uint32_t target = 384;               // 1/4 sample -> expected survivors ~1536

    for (int attempt = 0; attempt < 2; attempt++) {
        for (int i = tid; i < 4096; i += 1024) hist[i] = 0;
        if (tid == 0) s_cnt = 0;
        __syncthreads();

        if (use_sample) {
            float4 v = row4[tid * 4];
            atomicAdd(&hist[f2mk(v.x) >> 20], 1u);
            atomicAdd(&hist[f2mk(v.y) >> 20], 1u);
            atomicAdd(&hist[f2mk(v.z) >> 20], 1u);
            atomicAdd(&hist[f2mk(v.w) >> 20], 1u);
        } else {
#pragma unroll
            for (int s = 0; s < 4; s++) {
                float4 v = row4[tid + s * 1024];
                atomicAdd(&hist[f2mk(v.x) >> 20], 1u);
                atomicAdd(&hist[f2mk(v.y) >> 20], 1u);
                atomicAdd(&hist[f2mk(v.z) >> 20], 1u);
                atomicAdd(&hist[f2mk(v.w) >> 20], 1u);
            }
        }
        __syncthreads();

        if (tid < 256) {
            uint32_t cs = 0;
#pragma unroll
            for (int b = tid * 16; b < tid * 16 + 16; b++) cs += hist[b];
            chunksum[tid] = cs;
        }
        __syncthreads();
        for (int off = 1; off < 256; off <<= 1) {
            uint32_t add = 0;
            if (tid < 256 && tid + off < 256) add = chunksum[tid + off];
            __syncthreads();
            if (tid < 256) chunksum[tid] += add;
            __syncthreads();
        }
        if (tid < 256) {
            uint32_t Sc = chunksum[tid];
            uint32_t Sn = (tid < 255) ? chunksum[tid + 1] : 0;
            if (Sc >= target && Sn < target) {
                uint32_t cum = Sn;
                int b;
                for (b = tid * 16 + 15; b > tid * 16; b--) {
                    cum += hist[b];
                    if (cum >= target) break;
                }
                s_bstar = (uint32_t)b;
            }
        }
        __syncthreads();
        const uint32_t bstar = s_bstar;

        // compaction: warp-aggregated, writes contiguous within warp (coalesced)
#pragma unroll
        for (int s = 0; s < 4; s++) {
            const int i4 = tid + s * 1024;
            float4 vv = row4[i4];
            float vals[4] = {vv.x, vv.y, vv.z, vv.w};
#pragma unroll
            for (int e = 0; e < 4; e++) {
                uint32_t mk = f2mk(vals[e]);
                bool pred = (mk >> 20) >= bstar;
                uint32_t bal = __ballot_sync(0xFFFFFFFFu, pred);
                uint32_t base = 0;
                if (lane == 0 && bal)
                    base = atomicAdd(&s_cnt, (uint32_t)__popc(bal));
                base = __shfl_sync(0xFFFFFFFFu, base, 0);
                if (pred) {
                    uint32_t pos = base + (uint32_t)__popc(bal & lt_mask);
                    if (pos < 2048) {
                        uint32_t idx = (uint32_t)(i4 * 4 + e);
                        gp[pos] = ((unsigned long long)mk << 32) |
                                  (unsigned long long)(0xFFFFFFFFu - idx);
                    }
                }
            }
        }
        __syncthreads();
        cnt = s_cnt;
        if (cnt >= (uint32_t)TOPK && cnt <= 2048u) break;
        use_sample = false;
        target = TOPK;
        __syncthreads();
    }
    if (cnt > 2048u) cnt = 2048u;

    for (int i = tid; i < 2048; i += 1024)
        if ((uint32_t)i >= cnt) gp[i] = 0ull;
}

// ---------------- kernel T: sort survivors + softmax + mask -----------------
__global__ void __launch_bounds__(512)
sort_kernel(const unsigned long long* __restrict__ gpairs,
            const int* __restrict__ budget,
            float* __restrict__ out_idx, float* __restrict__ out_w,
            float* __restrict__ out_m)
{
    __shared__ unsigned long long pairs[2048];
    __shared__ float s_red[512];

    const int t   = blockIdx.x;
    const int tid = threadIdx.x;
    const unsigned long long* gp = gpairs + (size_t)t * 2048;

    unsigned long long v[4];
    {
        ulonglong2 q0 = ((const ulonglong2*)gp)[2 * tid];
        ulonglong2 q1 = ((const ulonglong2*)gp)[2 * tid + 1];
        v[0] = q0.x; v[1] = q0.y; v[2] = q1.x; v[3] = q1.y;
    }

    // ---- hybrid bitonic sort, 2048 u64 descending; 4 elems/thread ----------
    local_j1(v, true, false);                                  // k=2
    { bool d = ((tid & 1) == 0);                               // k=4
      local_j2(v, d); local_j1(v, d, d); }
    { bool d = ((tid & 2) == 0);                               // k=8
      shfl_stage(v, 1, d, tid);
      local_j2(v, d); local_j1(v, d, d); }
    { bool d = ((tid & 4) == 0);                               // k=16
      shfl_stage(v, 2, d, tid); shfl_stage(v, 1, d, tid);
      local_j2(v, d); local_j1(v, d, d); }
    { bool d = ((tid & 8) == 0);                               // k=32
      shfl_stage(v, 4, d, tid); shfl_stage(v, 2, d, tid); shfl_stage(v, 1, d, tid);
      local_j2(v, d); local_j1(v, d, d); }
    { bool d = ((tid & 16) == 0);                              // k=64
      shfl_stage(v, 8, d, tid); shfl_stage(v, 4, d, tid);
      shfl_stage(v, 2, d, tid); shfl_stage(v, 1, d, tid);
      local_j2(v, d); local_j1(v, d, d); }
    { bool d = ((tid & 32) == 0);                              // k=128
      merge128(v, d, tid); }

    { bool d = ((tid & 64) == 0);                              // k=256
      smem_stage(pairs, v, 128, d, tid);
      merge128(v, d, tid); }
    { bool d = ((tid & 128) == 0);                             // k=512
      smem_stage(pairs, v, 256, d, tid);
      smem_stage(pairs, v, 128, d, tid);
      merge128(v, d, tid); }
    { bool d = ((tid & 256) == 0);                             // k=1024
      smem_stage(pairs, v, 512, d, tid);
      smem_stage(pairs, v, 256, d, tid);
      smem_stage(pairs, v, 128, d, tid);
      merge128(v, d, tid); }
    {                                                          // k=2048 (desc)
      smem_stage(pairs, v, 1024, true, tid);
      smem_stage(pairs, v,  512, true, tid);
      smem_stage(pairs, v,  256, true, tid);
      smem_stage(pairs, v,  128, true, tid);
      merge128(v, true, tid); }

#pragma unroll
    for (int e = 0; e < 4; e++) pairs[swz(4 * tid + e)] = v[e];
    __syncthreads();

    // ---- softmax over sorted top-1024 + budget mask -------------------------
    const float vmax = mk2f((uint32_t)(pairs[swz(0)] >> 32));
    unsigned long long p0 = pairs[swz(tid)];
    unsigned long long p1 = pairs[swz(tid + 512)];
    float e0 = expf(mk2f((uint32_t)(p0 >> 32)) - vmax);
    float e1 = expf(mk2f((uint32_t)(p1 >> 32)) - vmax);
    s_red[tid] = e0 + e1;
    __syncthreads();
    for (int o = 256; o; o >>= 1) {
        if (tid < o) s_red[tid] += s_red[tid + o];
        __syncthreads();
    }
    const float inv = 1.f / s_red[0];

    const int bud = budget[t];
    const size_t base = (size_t)t * TOPK;
    {
        uint32_t idx0 = 0xFFFFFFFFu - (uint32_t)(p0 & 0xFFFFFFFFull);
        float m0 = (tid < bud) ? 1.f : 0.f;
        out_idx[base + tid] = (float)idx0;
        out_w[base + tid]   = e0 * inv * m0;
        out_m[base + tid]   = m0;
        uint32_t idx1 = 0xFFFFFFFFu - (uint32_t)(p1 & 0xFFFFFFFFull);
        int jj = tid + 512;
        float m1 = (jj < bud) ? 1.f : 0.f;
        out_idx[base + jj] = (float)idx1;
        out_w[base + jj]   = e1 * inv * m1;
        out_m[base + jj]   = m1;
    }
}

// ---------------- launch -----------------------------------------------------
extern "C" void kernel_launch(void* const* d_in, const int* in_sizes, int n_in,
                              void* d_out, int out_size)
{
    const float* x   = (const float*)d_in[0];
    const float* w1c = (const float*)d_in[1];
    const float* b1c = (const float*)d_in[2];
    const float* w2c = (const float*)d_in[3];
    const float* b2c = (const float*)d_in[4];
    const float* ws1 = (const float*)d_in[5];
    const float* bs1 = (const float*)d_in[6];
    const float* ws2 = (const float*)d_in[7];
    const float* bs2 = (const float*)d_in[8];

    float* out     = (float*)d_out;
    float* out_idx = out;
    float* out_w   = out + (size_t)NTOK * TOPK;
    float* out_m   = out + 2 * (size_t)NTOK * TOPK;
    float* out_c   = out + 3 * (size_t)NTOK * TOPK;

    float *hs_p, *hc_p, *sc_p;
    unsigned long long* pr_p;
    int *bud_p;
    cudaGetSymbolAddress((void**)&hs_p,  g_hs);
    cudaGetSymbolAddress((void**)&hc_p,  g_hc);
    cudaGetSymbolAddress((void**)&sc_p,  g_scores);
    cudaGetSymbolAddress((void**)&pr_p,  g_pairs);
    cudaGetSymbolAddress((void**)&bud_p, g_budget);

    // hs = relu(x@ws1+bs1), hc = relu(x@w1c+b1c) in one launch
    small_gemms<<<dim3(3, NTOK / 128), 256>>>(x, ws1, bs1, w1c, b1c, hs_p, hc_p);
    // complexity + budgets
    complexity_kernel<<<NTOK / 8, 256>>>(hc_p, w2c, b2c, out_c, bud_p);
    // scores = hs @ ws2 + bs2
    sgemm2_bias<<<dim3(POOL / 128, NTOK / 128), 256>>>(hs_p, ws2, bs2, sc_p, POOL, HID);
    // top-k: select survivors, then sort + softmax + mask
    select_kernel<<<NTOK, 1024>>>(sc_p, pr_p);
    sort_kernel<<<NTOK, 512>>>(pr_p, bud_p, out_idx, out_w, out_m);
}

// round 8
// speedup vs baseline: 1.2681x; 1.2681x over previous
#include <cuda_runtime.h>
#include <cstdint>
#include <math.h>

#define NTOK 8192
#define DIM  1024
#define HID  256
#define HIDC 128
#define POOL 16384
#define TOPK 1024

// ---------------- scratch (device globals: no allocations allowed) ----------
__device__ float g_hs[NTOK * HID];                              // 8 MB
__device__ float g_hc[NTOK * HIDC];                             // 4 MB
__device__ float g_scores[(size_t)NTOK * POOL];                 // 512 MB
__device__ int   g_budget[NTOK];

// packed fp32x2 FMA (sm_100+): two independent rn-rounded fp32 FMAs per issue.
__device__ __forceinline__ float2 ffma2(float2 a, float2 b, float2 c) {
    unsigned long long A = *(unsigned long long*)&a;
    unsigned long long B = *(unsigned long long*)&b;
    unsigned long long C = *(unsigned long long*)&c;
    unsigned long long D;
    asm("fma.rn.f32x2 %0, %1, %2, %3;" : "=l"(D) : "l"(A), "l"(B), "l"(C));
    return *(float2*)&D;
}

// ---------------- fp32x2 GEMM core (proven R2 version) ----------------------
template<bool RELU>
__device__ __forceinline__ void gemm_body(const float* __restrict__ A,
                                          const float* __restrict__ B,
                                          const float* __restrict__ bias,
                                          float* __restrict__ C,
                                          int N, int K, int bm, int bn,
                                          float Asm[2][8][128], float Bsm[2][8][128])
{
    const int tid = threadIdx.x;
    const int tx  = tid & 15;
    const int ty  = tid >> 4;

    float2 acc[8][4];
#pragma unroll
    for (int i = 0; i < 8; i++)
#pragma unroll
        for (int q = 0; q < 4; q++) acc[i][q] = make_float2(0.f, 0.f);

    const int ar = tid >> 1;
    const int ac = (tid & 1) * 4;
    const int br = tid >> 5;
    const int bc = (tid & 31) * 4;
    const float* Aptr = A + (size_t)(bm + ar) * K + ac;
    const float* Bptr = B + (size_t)br * N + bn + bc;

    const int NT = K >> 3;

    float4 av = *(const float4*)(Aptr);
    float4 bv = *(const float4*)(Bptr);
    Asm[0][ac + 0][ar] = av.x; Asm[0][ac + 1][ar] = av.y;
    Asm[0][ac + 2][ar] = av.z; Asm[0][ac + 3][ar] = av.w;
    *(float4*)&Bsm[0][br][bc] = bv;
    __syncthreads();

    for (int t = 0; t < NT; t++) {
        const int buf = t & 1;
        const bool more = (t + 1) < NT;
        if (more) {
            av = *(const float4*)(Aptr + (t + 1) * 8);
            bv = *(const float4*)(Bptr + (size_t)(t + 1) * 8 * N);
        }

#pragma unroll
        for (int k = 0; k < 8; k++) {
            float4 a0 = *(const float4*)&Asm[buf][k][ty * 8];
            float4 a1 = *(const float4*)&Asm[buf][k][ty * 8 + 4];
            float4 b0 = *(const float4*)&Bsm[buf][k][tx * 4];
            float4 b1 = *(const float4*)&Bsm[buf][k][tx * 4 + 64];
            float2 bp[4];
            bp[0] = make_float2(b0.x, b0.y); bp[1] = make_float2(b0.z, b0.w);
            bp[2] = make_float2(b1.x, b1.y); bp[3] = make_float2(b1.z, b1.w);
            float a[8] = {a0.x, a0.y, a0.z, a0.w, a1.x, a1.y, a1.z, a1.w};
#pragma unroll
            for (int i = 0; i < 8; i++) {
                float2 ad = make_float2(a[i], a[i]);
#pragma unroll
                for (int q = 0; q < 4; q++)
                    acc[i][q] = ffma2(ad, bp[q], acc[i][q]);
            }
        }

        if (more) {
            const int nb = buf ^ 1;
            Asm[nb][ac + 0][ar] = av.x; Asm[nb][ac + 1][ar] = av.y;
            Asm[nb][ac + 2][ar] = av.z; Asm[nb][ac + 3][ar] = av.w;
            *(float4*)&Bsm[nb][br][bc] = bv;
        }
        __syncthreads();
    }

#pragma unroll
    for (int i = 0; i < 8; i++) {
        const int row = bm + ty * 8 + i;
#pragma unroll
        for (int g = 0; g < 2; g++) {
            const int col = bn + tx * 4 + g * 64;
            float4 v;
            v.x = acc[i][g * 2 + 0].x + bias[col + 0];
            v.y = acc[i][g * 2 + 0].y + bias[col + 1];
            v.z = acc[i][g * 2 + 1].x + bias[col + 2];
            v.w = acc[i][g * 2 + 1].y + bias[col + 3];
            if (RELU) {
                v.x = fmaxf(v.x, 0.f); v.y = fmaxf(v.y, 0.f);
                v.z = fmaxf(v.z, 0.f); v.w = fmaxf(v.w, 0.f);
            }
            *(float4*)(C + (size_t)row * N + col) = v;
        }
    }
}

__global__ void __launch_bounds__(256, 2)
sgemm2_bias(const float* __restrict__ A, const float* __restrict__ B,
            const float* __restrict__ bias, float* __restrict__ C,
            int N, int K)
{
    __shared__ float As[2][8][128];
    __shared__ float Bs[2][8][128];
    gemm_body<false>(A, B, bias, C, N, K, blockIdx.y * 128, blockIdx.x * 128, As, Bs);
}

__global__ void __launch_bounds__(256, 2)
small_gemms(const float* __restrict__ x,
            const float* __restrict__ ws1, const float* __restrict__ bs1,
            const float* __restrict__ w1c, const float* __restrict__ b1c,
            float* __restrict__ hs, float* __restrict__ hc)
{
    __shared__ float As[2][8][128];
    __shared__ float Bs[2][8][128];
    const int bx = blockIdx.x;
    if (bx < 2)
        gemm_body<true>(x, ws1, bs1, hs, HID,  DIM, blockIdx.y * 128, bx * 128, As, Bs);
    else
        gemm_body<true>(x, w1c, b1c, hc, HIDC, DIM, blockIdx.y * 128, 0, As, Bs);
}

// ---------------- complexity -> sigmoid -> budget ---------------------------
__global__ void complexity_kernel(const float* __restrict__ hc,
                                  const float* __restrict__ w2c,
                                  const float* __restrict__ b2c,
                                  float* __restrict__ out_c,
                                  int* __restrict__ budget)
{
    int warp = (blockIdx.x * blockDim.x + threadIdx.x) >> 5;
    int lane = threadIdx.x & 31;
    if (warp >= NTOK) return;
    const float* h = hc + (size_t)warp * HIDC;
    float s = 0.f;
#pragma unroll
    for (int i = lane; i < HIDC; i += 32) s += h[i] * w2c[i];
#pragma unroll
    for (int o = 16; o; o >>= 1) s += __shfl_xor_sync(0xFFFFFFFFu, s, o);
    if (lane == 0) {
        float z = s + b2c[0];
        float c = 1.f / (1.f + expf(-z));
        out_c[warp] = c;
        float raw = 100.f + 924.f * (c * c);
        raw = fminf(fmaxf(raw, 100.f), 1024.f);
        budget[warp] = (int)rintf(raw);
    }
}

// ---------------- top-k helpers ---------------------------------------------
__device__ __forceinline__ uint32_t f2mk(float f) {
    uint32_t u = __float_as_uint(f);
    return (u & 0x80000000u) ? ~u : (u | 0x80000000u);
}
__device__ __forceinline__ float mk2f(uint32_t mk) {
    uint32_t u = (mk & 0x80000000u) ? (mk ^ 0x80000000u) : ~mk;
    return __uint_as_float(u);
}

// ---------------- fused top-k: threshold select + counting sort -------------
// smem layout (dynamic, 52 KB):
//   staging[2048] u64 | final[2048] u64 | hist[4096] u32 | chunksum[256] u32 |
//   s_red[512] f32 | scalars[4] u32 (bstar, cnt, flag)
__global__ void __launch_bounds__(512)
topk_kernel(const float* __restrict__ scores, const int* __restrict__ budget,
            float* __restrict__ out_idx, float* __restrict__ out_w,
            float* __restrict__ out_m)
{
    extern __shared__ char smem_raw[];
    unsigned long long* staging = (unsigned long long*)smem_raw;
    unsigned long long* fin     = staging + 2048;
    uint32_t* hist     = (uint32_t*)(fin + 2048);
    uint32_t* chunksum = hist + 4096;
    float*    s_red    = (float*)(chunksum + 256);
    uint32_t* scal     = (uint32_t*)(s_red + 512);
    #define S_BSTAR scal[0]
    #define S_CNT   scal[1]
    #define S_FLAG  scal[2]

    const int t    = blockIdx.x;
    const int tid  = threadIdx.x;
    const int lane = tid & 31;
    const uint32_t lt_mask = (1u << lane) - 1u;
    const float4* row4 = (const float4*)(scores + (size_t)t * POOL);

    uint32_t cnt = 0, bstar = 0;
    bool     use_sample = true;
    uint32_t target = 192;               // 1/8 sample -> expected survivors ~1536

    for (int attempt = 0; attempt < 2; attempt++) {
        for (int i = tid; i < 4096; i += 512) hist[i] = 0;
        if (tid == 0) S_CNT = 0;
        __syncthreads();

        // coarse (12-bit) histogram: sampled or exact
        if (use_sample) {
            float4 v = row4[tid * 8];     // every 8th float4 -> 2048 samples
            atomicAdd(&hist[f2mk(v.x) >> 20], 1u);
            atomicAdd(&hist[f2mk(v.y) >> 20], 1u);
            atomicAdd(&hist[f2mk(v.z) >> 20], 1u);
            atomicAdd(&hist[f2mk(v.w) >> 20], 1u);
        } else {
#pragma unroll
            for (int s = 0; s < 8; s++) {
                float4 v = row4[tid + s * 512];
                atomicAdd(&hist[f2mk(v.x) >> 20], 1u);
                atomicAdd(&hist[f2mk(v.y) >> 20], 1u);
                atomicAdd(&hist[f2mk(v.z) >> 20], 1u);
                atomicAdd(&hist[f2mk(v.w) >> 20], 1u);
            }
        }
        __syncthreads();

        // suffix scan over 256 chunks of 16 bins
        if (tid < 256) {
            uint32_t cs = 0;
#pragma unroll
            for (int b = tid * 16; b < tid * 16 + 16; b++) cs += hist[b];
            chunksum[tid] = cs;
        }
        __syncthreads();
        for (int off = 1; off < 256; off <<= 1) {
            uint32_t add = 0;
            if (tid < 256 && tid + off < 256) add = chunksum[tid + off];
            __syncthreads();
            if (tid < 256) chunksum[tid] += add;
            __syncthreads();
        }
        if (tid < 256) {
            uint32_t Sc = chunksum[tid];
            uint32_t Sn = (tid < 255) ? chunksum[tid + 1] : 0;
            if (Sc >= target && Sn < target) {
                uint32_t cum = Sn;
                int b;
                for (b = tid * 16 + 15; b > tid * 16; b--) {
                    cum += hist[b];
                    if (cum >= target) break;
                }
                S_BSTAR = (uint32_t)b;
            }
        }
        __syncthreads();
        bstar = S_BSTAR;

        // clear hist for reuse as FINE histogram of survivors
        for (int i = tid; i < 4096; i += 512) hist[i] = 0;
        __syncthreads();

        // compact survivors to staging + build fine histogram
        // fine bin: 7 extra mantissa bits relative to bstar (monotonic, clamped)
#pragma unroll
        for (int s = 0; s < 8; s++) {
            const int i4 = tid + s * 512;
            float4 vv = row4[i4];
            float vals[4] = {vv.x, vv.y, vv.z, vv.w};
#pragma unroll
            for (int e = 0; e < 4; e++) {
                uint32_t mk = f2mk(vals[e]);
                bool pred = (mk >> 20) >= bstar;
                uint32_t bal = __ballot_sync(0xFFFFFFFFu, pred);
                uint32_t base = 0;
                if (lane == 0 && bal)
                    base = atomicAdd(&S_CNT, (uint32_t)__popc(bal));
                base = __shfl_sync(0xFFFFFFFFu, base, 0);
                if (pred) {
                    uint32_t pos = base + (uint32_t)__popc(bal & lt_mask);
                    if (pos < 2048) {
                        uint32_t idx = (uint32_t)(i4 * 4 + e);
                        staging[pos] = ((unsigned long long)mk << 32) |
                                       (unsigned long long)(0xFFFFFFFFu - idx);
                        uint32_t rel = mk - (bstar << 20);
                        uint32_t fb  = rel >> 13;
                        if (fb > 4095u) fb = 4095u;
                        atomicAdd(&hist[fb], 1u);
                    }
                }
            }
        }
        __syncthreads();
        cnt = S_CNT;
        if (cnt >= (uint32_t)TOPK && cnt <= 2048u) break;
        use_sample = false;
        target = TOPK;
        __syncthreads();
    }
    if (cnt > 2048u) cnt = 2048u;

    // suffix-scan fine hist -> per-bin scatter bases (desc order: higher bin first)
    if (tid < 256) {
        uint32_t cs = 0;
#pragma unroll
        for (int b = tid * 16; b < tid * 16 + 16; b++) cs += hist[b];
        chunksum[tid] = cs;
    }
    __syncthreads();
    for (int off = 1; off < 256; off <<= 1) {
        uint32_t add = 0;
        if (tid < 256 && tid + off < 256) add = chunksum[tid + off];
        __syncthreads();
        if (tid < 256) chunksum[tid] += add;
        __syncthreads();
    }
    if (tid < 256) {
        uint32_t acc = (tid < 255) ? chunksum[tid + 1] : 0;   // count in higher chunks
        for (int b = tid * 16 + 15; b >= tid * 16; b--) {
            uint32_t c = hist[b];
            hist[b] = acc;          // base for bin b = count of survivors in bins > b
            acc += c;
        }
    }
    __syncthreads();

    // scatter into near-sorted position; pad tail
    for (int i = tid; i < 2048; i += 512) {
        if ((uint32_t)i < cnt) {
            unsigned long long k = staging[i];
            uint32_t mk  = (uint32_t)(k >> 32);
            uint32_t rel = mk - (bstar << 20);
            uint32_t fb  = rel >> 13;
            if (fb > 4095u) fb = 4095u;
            uint32_t pos = atomicAdd(&hist[fb], 1u);
            fin[pos] = k;
        } else {
            fin[i] = 0ull;
        }
    }
    __syncthreads();

    // odd-even transposition until fully sorted (fixes intra-bin order only;
    // unique keys -> unique deterministic result)
    while (true) {
        if (tid == 0) S_FLAG = 0;
        __syncthreads();
#pragma unroll
        for (int r = 0; r < 2; r++) {          // even pairs (2i, 2i+1)
            int i = tid + r * 512;
            unsigned long long a = fin[2 * i], b = fin[2 * i + 1];
            if (a < b) { fin[2 * i] = b; fin[2 * i + 1] = a; S_FLAG = 1; }
        }
        __syncthreads();
#pragma unroll
        for (int r = 0; r < 2; r++) {          // odd pairs (2i+1, 2i+2)
            int i = tid + r * 512;
            if (i < 1023) {
                unsigned long long a = fin[2 * i + 1], b = fin[2 * i + 2];
                if (a < b) { fin[2 * i + 1] = b; fin[2 * i + 2] = a; S_FLAG = 1; }
            }
        }
        __syncthreads();
        uint32_t f = S_FLAG;
        __syncthreads();
        if (!f) break;
    }

    // softmax over sorted top-1024 + budget mask
    const float vmax = mk2f((uint32_t)(fin[0] >> 32));
    unsigned long long p0 = fin[tid];
    unsigned long long p1 = fin[tid + 512];
    float e0 = expf(mk2f((uint32_t)(p0 >> 32)) - vmax);
    float e1 = expf(mk2f((uint32_t)(p1 >> 32)) - vmax);
    s_red[tid] = e0 + e1;
    __syncthreads();
    for (int o = 256; o; o >>= 1) {
        if (tid < o) s_red[tid] += s_red[tid + o];
        __syncthreads();
    }
    const float inv = 1.f / s_red[0];

    const int bud = budget[t];
    const size_t base = (size_t)t * TOPK;
    {
        uint32_t idx0 = 0xFFFFFFFFu - (uint32_t)(p0 & 0xFFFFFFFFull);
        float m0 = (tid < bud) ? 1.f : 0.f;
        out_idx[base + tid] = (float)idx0;
        out_w[base + tid]   = e0 * inv * m0;
        out_m[base + tid]   = m0;
        uint32_t idx1 = 0xFFFFFFFFu - (uint32_t)(p1 & 0xFFFFFFFFull);
        int jj = tid + 512;
        float m1 = (jj < bud) ? 1.f : 0.f;
        out_idx[base + jj] = (float)idx1;
        out_w[base + jj]   = e1 * inv * m1;
        out_m[base + jj]   = m1;
    }
    #undef S_BSTAR
    #undef S_CNT
    #undef S_FLAG
}

// ---------------- launch -----------------------------------------------------
extern "C" void kernel_launch(void* const* d_in, const int* in_sizes, int n_in,
                              void* d_out, int out_size)
{
    const float* x   = (const float*)d_in[0];
    const float* w1c = (const float*)d_in[1];
    const float* b1c = (const float*)d_in[2];
    const float* w2c = (const float*)d_in[3];
    const float* b2c = (const float*)d_in[4];
    const float* ws1 = (const float*)d_in[5];
    const float* bs1 = (const float*)d_in[6];
    const float* ws2 = (const float*)d_in[7];
    const float* bs2 = (const float*)d_in[8];

    float* out     = (float*)d_out;
    float* out_idx = out;
    float* out_w   = out + (size_t)NTOK * TOPK;
    float* out_m   = out + 2 * (size_t)NTOK * TOPK;
    float* out_c   = out + 3 * (size_t)NTOK * TOPK;

    float *hs_p, *hc_p, *sc_p;
    int *bud_p;
    cudaGetSymbolAddress((void**)&hs_p,  g_hs);
    cudaGetSymbolAddress((void**)&hc_p,  g_hc);
    cudaGetSymbolAddress((void**)&sc_p,  g_scores);
    cudaGetSymbolAddress((void**)&bud_p, g_budget);

    const int TOPK_SMEM = 53248;   // 52 KB dynamic
    static bool attr_set = false;
    if (!attr_set) {
        cudaFuncSetAttribute(topk_kernel,
                             cudaFuncAttributeMaxDynamicSharedMemorySize, TOPK_SMEM);
        attr_set = true;
    }

    small_gemms<<<dim3(3, NTOK / 128), 256>>>(x, ws1, bs1, w1c, b1c, hs_p, hc_p);
    complexity_kernel<<<NTOK / 8, 256>>>(hc_p, w2c, b2c, out_c, bud_p);
    sgemm2_bias<<<dim3(POOL / 128, NTOK / 128), 256>>>(hs_p, ws2, bs2, sc_p, POOL, HID);
    topk_kernel<<<NTOK, 512, TOPK_SMEM>>>(sc_p, bud_p, out_idx, out_w, out_m);
}

// round 9
// speedup vs baseline: 1.2826x; 1.0114x over previous
#include <cuda_runtime.h>
#include <cstdint>
#include <math.h>

#define NTOK 8192
#define DIM  1024
#define HID  256
#define HIDC 128
#define POOL 16384
#define TOPK 1024

// ---------------- scratch (device globals: no allocations allowed) ----------
__device__ float g_hs[NTOK * HID];                              // 8 MB
__device__ float g_hc[NTOK * HIDC];                             // 4 MB
__device__ float g_scores[(size_t)NTOK * POOL];                 // 512 MB
__device__ int   g_budget[NTOK];

// packed fp32x2 FMA (sm_100+): two independent rn-rounded fp32 FMAs per issue.
__device__ __forceinline__ float2 ffma2(float2 a, float2 b, float2 c) {
    unsigned long long A = *(unsigned long long*)&a;
    unsigned long long B = *(unsigned long long*)&b;
    unsigned long long C = *(unsigned long long*)&c;
    unsigned long long D;
    asm("fma.rn.f32x2 %0, %1, %2, %3;" : "=l"(D) : "l"(A), "l"(B), "l"(C));
    return *(float2*)&D;
}

// ---------------- fp32x2 GEMM core (proven R2 version) ----------------------
template<bool RELU>
__device__ __forceinline__ void gemm_body(const float* __restrict__ A,
                                          const float* __restrict__ B,
                                          const float* __restrict__ bias,
                                          float* __restrict__ C,
                                          int N, int K, int bm, int bn,
                                          float Asm[2][8][128], float Bsm[2][8][128])
{
    const int tid = threadIdx.x;
    const int tx  = tid & 15;
    const int ty  = tid >> 4;

    float2 acc[8][4];
#pragma unroll
    for (int i = 0; i < 8; i++)
#pragma unroll
        for (int q = 0; q < 4; q++) acc[i][q] = make_float2(0.f, 0.f);

    const int ar = tid >> 1;
    const int ac = (tid & 1) * 4;
    const int br = tid >> 5;
    const int bc = (tid & 31) * 4;
    const float* Aptr = A + (size_t)(bm + ar) * K + ac;
    const float* Bptr = B + (size_t)br * N + bn + bc;

    const int NT = K >> 3;

    float4 av = *(const float4*)(Aptr);
    float4 bv = *(const float4*)(Bptr);
    Asm[0][ac + 0][ar] = av.x; Asm[0][ac + 1][ar] = av.y;
    Asm[0][ac + 2][ar] = av.z; Asm[0][ac + 3][ar] = av.w;
    *(float4*)&Bsm[0][br][bc] = bv;
    __syncthreads();

    for (int t = 0; t < NT; t++) {
        const int buf = t & 1;
        const bool more = (t + 1) < NT;
        if (more) {
            av = *(const float4*)(Aptr + (t + 1) * 8);
            bv = *(const float4*)(Bptr + (size_t)(t + 1) * 8 * N);
        }

#pragma unroll
        for (int k = 0; k < 8; k++) {
            float4 a0 = *(const float4*)&Asm[buf][k][ty * 8];
            float4 a1 = *(const float4*)&Asm[buf][k][ty * 8 + 4];
            float4 b0 = *(const float4*)&Bsm[buf][k][tx * 4];
            float4 b1 = *(const float4*)&Bsm[buf][k][tx * 4 + 64];
            float2 bp[4];
            bp[0] = make_float2(b0.x, b0.y); bp[1] = make_float2(b0.z, b0.w);
            bp[2] = make_float2(b1.x, b1.y); bp[3] = make_float2(b1.z, b1.w);
            float a[8] = {a0.x, a0.y, a0.z, a0.w, a1.x, a1.y, a1.z, a1.w};
#pragma unroll
            for (int i = 0; i < 8; i++) {
                float2 ad = make_float2(a[i], a[i]);
#pragma unroll
                for (int q = 0; q < 4; q++)
                    acc[i][q] = ffma2(ad, bp[q], acc[i][q]);
            }
        }

        if (more) {
            const int nb = buf ^ 1;
            Asm[nb][ac + 0][ar] = av.x; Asm[nb][ac + 1][ar] = av.y;
            Asm[nb][ac + 2][ar] = av.z; Asm[nb][ac + 3][ar] = av.w;
            *(float4*)&Bsm[nb][br][bc] = bv;
        }
        __syncthreads();
    }

#pragma unroll
    for (int i = 0; i < 8; i++) {
        const int row = bm + ty * 8 + i;
#pragma unroll
        for (int g = 0; g < 2; g++) {
            const int col = bn + tx * 4 + g * 64;
            float4 v;
            v.x = acc[i][g * 2 + 0].x + bias[col + 0];
            v.y = acc[i][g * 2 + 0].y + bias[col + 1];
            v.z = acc[i][g * 2 + 1].x + bias[col + 2];
            v.w = acc[i][g * 2 + 1].y + bias[col + 3];
            if (RELU) {
                v.x = fmaxf(v.x, 0.f); v.y = fmaxf(v.y, 0.f);
                v.z = fmaxf(v.z, 0.f); v.w = fmaxf(v.w, 0.f);
            }
            *(float4*)(C + (size_t)row * N + col) = v;
        }
    }
}

__global__ void __launch_bounds__(256, 2)
sgemm2_bias(const float* __restrict__ A, const float* __restrict__ B,
            const float* __restrict__ bias, float* __restrict__ C,
            int N, int K)
{
    __shared__ float As[2][8][128];
    __shared__ float Bs[2][8][128];
    gemm_body<false>(A, B, bias, C, N, K, blockIdx.y * 128, blockIdx.x * 128, As, Bs);
}

__global__ void __launch_bounds__(256, 2)
small_gemms(const float* __restrict__ x,
            const float* __restrict__ ws1, const float* __restrict__ bs1,
            const float* __restrict__ w1c, const float* __restrict__ b1c,
            float* __restrict__ hs, float* __restrict__ hc)
{
    __shared__ float As[2][8][128];
    __shared__ float Bs[2][8][128];
    const int bx = blockIdx.x;
    if (bx < 2)
        gemm_body<true>(x, ws1, bs1, hs, HID,  DIM, blockIdx.y * 128, bx * 128, As, Bs);
    else
        gemm_body<true>(x, w1c, b1c, hc, HIDC, DIM, blockIdx.y * 128, 0, As, Bs);
}

// ---------------- complexity -> sigmoid -> budget ---------------------------
__global__ void complexity_kernel(const float* __restrict__ hc,
                                  const float* __restrict__ w2c,
                                  const float* __restrict__ b2c,
                                  float* __restrict__ out_c,
                                  int* __restrict__ budget)
{
    int warp = (blockIdx.x * blockDim.x + threadIdx.x) >> 5;
    int lane = threadIdx.x & 31;
    if (warp >= NTOK) return;
    const float* h = hc + (size_t)warp * HIDC;
    float s = 0.f;
#pragma unroll
    for (int i = lane; i < HIDC; i += 32) s += h[i] * w2c[i];
#pragma unroll
    for (int o = 16; o; o >>= 1) s += __shfl_xor_sync(0xFFFFFFFFu, s, o);
    if (lane == 0) {
        float z = s + b2c[0];
        float c = 1.f / (1.f + expf(-z));
        out_c[warp] = c;
        float raw = 100.f + 924.f * (c * c);
        raw = fminf(fmaxf(raw, 100.f), 1024.f);
        budget[warp] = (int)rintf(raw);
    }
}

// ---------------- top-k helpers ---------------------------------------------
__device__ __forceinline__ uint32_t f2mk(float f) {
    uint32_t u = __float_as_uint(f);
    return (u & 0x80000000u) ? ~u : (u | 0x80000000u);
}
__device__ __forceinline__ float mk2f(uint32_t mk) {
    uint32_t u = (mk & 0x80000000u) ? (mk ^ 0x80000000u) : ~mk;
    return __uint_as_float(u);
}

// ---------------- fused top-k: threshold select + counting sort -------------
// smem layout (dynamic, 52 KB):
//   staging[2048] u64 | final[2048] u64 | hist[4096] u32 | chunksum[256] u32 |
//   s_red[512] f32 | scalars[4] u32
__global__ void __launch_bounds__(512)
topk_kernel(const float* __restrict__ scores, const int* __restrict__ budget,
            float* __restrict__ out_idx, float* __restrict__ out_w,
            float* __restrict__ out_m)
{
    extern __shared__ char smem_raw[];
    unsigned long long* staging = (unsigned long long*)smem_raw;
    unsigned long long* fin     = staging + 2048;
    uint32_t* hist     = (uint32_t*)(fin + 2048);
    uint32_t* chunksum = hist + 4096;
    float*    s_red    = (float*)(chunksum + 256);
    uint32_t* s_redu   = (uint32_t*)s_red;
    uint32_t* scal     = (uint32_t*)(s_red + 512);
    #define S_BSTAR scal[0]
    #define S_CNT   scal[1]

    const int t    = blockIdx.x;
    const int tid  = threadIdx.x;
    const int lane = tid & 31;
    const uint32_t lt_mask = (1u << lane) - 1u;
    const float4* row4 = (const float4*)(scores + (size_t)t * POOL);

    uint32_t cnt = 0, bstar = 0;
    bool     use_sample = true;
    uint32_t target = 192;               // 1/8 sample -> expected survivors ~1536

    for (int attempt = 0; attempt < 2; attempt++) {
        for (int i = tid; i < 4096; i += 512) hist[i] = 0;
        if (tid == 0) S_CNT = 0;
        __syncthreads();

        // coarse (12-bit) histogram: sampled or exact
        if (use_sample) {
            float4 v = row4[tid * 8];
            atomicAdd(&hist[f2mk(v.x) >> 20], 1u);
            atomicAdd(&hist[f2mk(v.y) >> 20], 1u);
            atomicAdd(&hist[f2mk(v.z) >> 20], 1u);
            atomicAdd(&hist[f2mk(v.w) >> 20], 1u);
        } else {
#pragma unroll
            for (int s = 0; s < 8; s++) {
                float4 v = row4[tid + s * 512];
                atomicAdd(&hist[f2mk(v.x) >> 20], 1u);
                atomicAdd(&hist[f2mk(v.y) >> 20], 1u);
                atomicAdd(&hist[f2mk(v.z) >> 20], 1u);
                atomicAdd(&hist[f2mk(v.w) >> 20], 1u);
            }
        }
        __syncthreads();

        // suffix scan over 256 chunks of 16 bins -> threshold bin bstar
        if (tid < 256) {
            uint32_t cs = 0;
#pragma unroll
            for (int b = tid * 16; b < tid * 16 + 16; b++) cs += hist[b];
            chunksum[tid] = cs;
        }
        __syncthreads();
        for (int off = 1; off < 256; off <<= 1) {
            uint32_t add = 0;
            if (tid < 256 && tid + off < 256) add = chunksum[tid + off];
            __syncthreads();
            if (tid < 256) chunksum[tid] += add;
            __syncthreads();
        }
        if (tid < 256) {
            uint32_t Sc = chunksum[tid];
            uint32_t Sn = (tid < 255) ? chunksum[tid + 1] : 0;
            if (Sc >= target && Sn < target) {
                uint32_t cum = Sn;
                int b;
                for (b = tid * 16 + 15; b > tid * 16; b--) {
                    cum += hist[b];
                    if (cum >= target) break;
                }
                S_BSTAR = (uint32_t)b;
            }
        }
        __syncthreads();
        bstar = S_BSTAR;

        // clear hist for reuse as FINE histogram of survivors
        for (int i = tid; i < 4096; i += 512) hist[i] = 0;
        __syncthreads();

        // compact survivors to staging + build fine histogram
#pragma unroll
        for (int s = 0; s < 8; s++) {
            const int i4 = tid + s * 512;
            float4 vv = row4[i4];
            float vals[4] = {vv.x, vv.y, vv.z, vv.w};
#pragma unroll
            for (int e = 0; e < 4; e++) {
                uint32_t mk = f2mk(vals[e]);
                bool pred = (mk >> 20) >= bstar;
                uint32_t bal = __ballot_sync(0xFFFFFFFFu, pred);
                uint32_t base = 0;
                if (lane == 0 && bal)
                    base = atomicAdd(&S_CNT, (uint32_t)__popc(bal));
                base = __shfl_sync(0xFFFFFFFFu, base, 0);
                if (pred) {
                    uint32_t pos = base + (uint32_t)__popc(bal & lt_mask);
                    if (pos < 2048) {
                        uint32_t idx = (uint32_t)(i4 * 4 + e);
                        staging[pos] = ((unsigned long long)mk << 32) |
                                       (unsigned long long)(0xFFFFFFFFu - idx);
                        uint32_t rel = mk - (bstar << 20);
                        uint32_t fb  = rel >> 13;
                        if (fb > 4095u) fb = 4095u;
                        atomicAdd(&hist[fb], 1u);
                    }
                }
            }
        }
        __syncthreads();
        cnt = S_CNT;
        if (cnt >= (uint32_t)TOPK && cnt <= 2048u) break;
        use_sample = false;
        target = TOPK;
        __syncthreads();
    }
    if (cnt > 2048u) cnt = 2048u;

    // suffix-scan fine hist -> per-bin scatter bases (desc order)
    if (tid < 256) {
        uint32_t cs = 0;
#pragma unroll
        for (int b = tid * 16; b < tid * 16 + 16; b++) cs += hist[b];
        chunksum[tid] = cs;
    }
    __syncthreads();
    for (int off = 1; off < 256; off <<= 1) {
        uint32_t add = 0;
        if (tid < 256 && tid + off < 256) add = chunksum[tid + off];
        __syncthreads();
        if (tid < 256) chunksum[tid] += add;
        __syncthreads();
    }
    if (tid < 256) {
        uint32_t acc = (tid < 255) ? chunksum[tid + 1] : 0;
        for (int b = tid * 16 + 15; b >= tid * 16; b--) {
            uint32_t c = hist[b];
            hist[b] = acc;          // base for bin b = count in bins > b
            acc += c;
        }
    }
    __syncthreads();

    // end = min{ base[fb] : base[fb] >= 1024 } -> exclusive end of the bin
    // containing rank 1023. Elements in bins with base >= end can't reach
    // the top-1024; skip them. (block tree-reduce)
    {
        uint32_t lmin = cnt;  // bases <= cnt; cnt >= 1024 guaranteed post-select
#pragma unroll
        for (int s = 0; s < 8; s++) {
            uint32_t b = hist[tid + s * 512];
            if (b >= (uint32_t)TOPK && b < lmin) lmin = b;
        }
        s_redu[tid] = lmin;
        __syncthreads();
        for (int o = 256; o; o >>= 1) {
            if (tid < o) {
                uint32_t a = s_redu[tid], b = s_redu[tid + o];
                s_redu[tid] = (b < a) ? b : a;
            }
            __syncthreads();
        }
    }
    const int end = (int)s_redu[0];
    __syncthreads();

    // scatter (only bins that intersect [0, end))
    for (int i = tid; i < (int)cnt; i += 512) {
        unsigned long long k = staging[i];
        uint32_t mk  = (uint32_t)(k >> 32);
        uint32_t rel = mk - (bstar << 20);
        uint32_t fb  = rel >> 13;
        if (fb > 4095u) fb = 4095u;
        // bins with base >= end lie entirely outside the top-1024 prefix
        if (hist[fb] < (uint32_t)end) {
            uint32_t pos = atomicAdd(&hist[fb], 1u);
            fin[pos] = k;
        }
    }
    __syncthreads();

    // odd-even transposition over [0, end) until sorted (intra-bin fixup)
    while (true) {
        int moved = 0;
#pragma unroll
        for (int r = 0; r < 2; r++) {          // even pairs (2i, 2i+1)
            int i = tid + r * 512;
            int p = 2 * i;
            if (p + 1 < end) {
                unsigned long long a = fin[p], b = fin[p + 1];
                if (a < b) { fin[p] = b; fin[p + 1] = a; moved = 1; }
            }
        }
        __syncthreads();
#pragma unroll
        for (int r = 0; r < 2; r++) {          // odd pairs (2i+1, 2i+2)
            int i = tid + r * 512;
            int p = 2 * i + 1;
            if (p + 1 < end) {
                unsigned long long a = fin[p], b = fin[p + 1];
                if (a < b) { fin[p] = b; fin[p + 1] = a; moved = 1; }
            }
        }
        if (!__syncthreads_or(moved)) break;
    }

    // softmax over sorted top-1024 + budget mask
    const float vmax = mk2f((uint32_t)(fin[0] >> 32));
    unsigned long long p0 = fin[tid];
    unsigned long long p1 = fin[tid + 512];
    float e0 = expf(mk2f((uint32_t)(p0 >> 32)) - vmax);
    float e1 = expf(mk2f((uint32_t)(p1 >> 32)) - vmax);
    s_red[tid] = e0 + e1;
    __syncthreads();
    for (int o = 256; o; o >>= 1) {
        if (tid < o) s_red[tid] += s_red[tid + o];
        __syncthreads();
    }
    const float inv = 1.f / s_red[0];

    const int bud = budget[t];
    const size_t base = (size_t)t * TOPK;
    {
        uint32_t idx0 = 0xFFFFFFFFu - (uint32_t)(p0 & 0xFFFFFFFFull);
        float m0 = (tid < bud) ? 1.f : 0.f;
        out_idx[base + tid] = (float)idx0;
        out_w[base + tid]   = e0 * inv * m0;
        out_m[base + tid]   = m0;
        uint32_t idx1 = 0xFFFFFFFFu - (uint32_t)(p1 & 0xFFFFFFFFull);
        int jj = tid + 512;
        float m1 = (jj < bud) ? 1.f : 0.f;
        out_idx[base + jj] = (float)idx1;
        out_w[base + jj]   = e1 * inv * m1;
        out_m[base + jj]   = m1;
    }
    #undef S_BSTAR
    #undef S_CNT
}

// ---------------- launch -----------------------------------------------------
extern "C" void kernel_launch(void* const* d_in, const int* in_sizes, int n_in,
                              void* d_out, int out_size)
{
    const float* x   = (const float*)d_in[0];
    const float* w1c = (const float*)d_in[1];
    const float* b1c = (const float*)d_in[2];
    const float* w2c = (const float*)d_in[3];
    const float* b2c = (const float*)d_in[4];
    const float* ws1 = (const float*)d_in[5];
    const float* bs1 = (const float*)d_in[6];
    const float* ws2 = (const float*)d_in[7];
    const float* bs2 = (const float*)d_in[8];

    float* out     = (float*)d_out;
    float* out_idx = out;
    float* out_w   = out + (size_t)NTOK * TOPK;
    float* out_m   = out + 2 * (size_t)NTOK * TOPK;
    float* out_c   = out + 3 * (size_t)NTOK * TOPK;

    float *hs_p, *hc_p, *sc_p;
    int *bud_p;
    cudaGetSymbolAddress((void**)&hs_p,  g_hs);
    cudaGetSymbolAddress((void**)&hc_p,  g_hc);
    cudaGetSymbolAddress((void**)&sc_p,  g_scores);
    cudaGetSymbolAddress((void**)&bud_p, g_budget);

    const int TOPK_SMEM = 53248;   // 52 KB dynamic
    static bool attr_set = false;
    if (!attr_set) {
        cudaFuncSetAttribute(topk_kernel,
                             cudaFuncAttributeMaxDynamicSharedMemorySize, TOPK_SMEM);
        attr_set = true;
    }

    small_gemms<<<dim3(3, NTOK / 128), 256>>>(x, ws1, bs1, w1c, b1c, hs_p, hc_p);
    complexity_kernel<<<NTOK / 8, 256>>>(hc_p, w2c, b2c, out_c, bud_p);
    sgemm2_bias<<<dim3(POOL / 128, NTOK / 128), 256>>>(hs_p, ws2, bs2, sc_p, POOL, HID);
    topk_kernel<<<NTOK, 512, TOPK_SMEM>>>(sc_p, bud_p, out_idx, out_w, out_m);
}

// round 10
// speedup vs baseline: 1.3370x; 1.0424x over previous
#include <cuda_runtime.h>
#include <cstdint>
#include <math.h>

#define NTOK 8192
#define DIM  1024
#define HID  256
#define HIDC 128
#define POOL 16384
#define TOPK 1024

// ---------------- scratch (device globals: no allocations allowed) ----------
__device__ float g_hs[NTOK * HID];                              // 8 MB
__device__ float g_hc[NTOK * HIDC];                             // 4 MB
__device__ float g_scores[(size_t)NTOK * POOL];                 // 512 MB
__device__ int   g_budget[NTOK];

// packed fp32x2 FMA (sm_100+): two independent rn-rounded fp32 FMAs per issue.
__device__ __forceinline__ float2 ffma2(float2 a, float2 b, float2 c) {
    unsigned long long A = *(unsigned long long*)&a;
    unsigned long long B = *(unsigned long long*)&b;
    unsigned long long C = *(unsigned long long*)&c;
    unsigned long long D;
    asm("fma.rn.f32x2 %0, %1, %2, %3;" : "=l"(D) : "l"(A), "l"(B), "l"(C));
    return *(float2*)&D;
}

// ---------------- fp32x2 GEMM core (proven R2 version) ----------------------
template<bool RELU>
__device__ __forceinline__ void gemm_body(const float* __restrict__ A,
                                          const float* __restrict__ B,
                                          const float* __restrict__ bias,
                                          float* __restrict__ C,
                                          int N, int K, int bm, int bn,
                                          float Asm[2][8][128], float Bsm[2][8][128])
{
    const int tid = threadIdx.x;
    const int tx  = tid & 15;
    const int ty  = tid >> 4;

    float2 acc[8][4];
#pragma unroll
    for (int i = 0; i < 8; i++)
#pragma unroll
        for (int q = 0; q < 4; q++) acc[i][q] = make_float2(0.f, 0.f);

    const int ar = tid >> 1;
    const int ac = (tid & 1) * 4;
    const int br = tid >> 5;
    const int bc = (tid & 31) * 4;
    const float* Aptr = A + (size_t)(bm + ar) * K + ac;
    const float* Bptr = B + (size_t)br * N + bn + bc;

    const int NT = K >> 3;

    float4 av = *(const float4*)(Aptr);
    float4 bv = *(const float4*)(Bptr);
    Asm[0][ac + 0][ar] = av.x; Asm[0][ac + 1][ar] = av.y;
    Asm[0][ac + 2][ar] = av.z; Asm[0][ac + 3][ar] = av.w;
    *(float4*)&Bsm[0][br][bc] = bv;
    __syncthreads();

    for (int t = 0; t < NT; t++) {
        const int buf = t & 1;
        const bool more = (t + 1) < NT;
        if (more) {
            av = *(const float4*)(Aptr + (t + 1) * 8);
            bv = *(const float4*)(Bptr + (size_t)(t + 1) * 8 * N);
        }

#pragma unroll
        for (int k = 0; k < 8; k++) {
            float4 a0 = *(const float4*)&Asm[buf][k][ty * 8];
            float4 a1 = *(const float4*)&Asm[buf][k][ty * 8 + 4];
            float4 b0 = *(const float4*)&Bsm[buf][k][tx * 4];
            float4 b1 = *(const float4*)&Bsm[buf][k][tx * 4 + 64];
            float2 bp[4];
            bp[0] = make_float2(b0.x, b0.y); bp[1] = make_float2(b0.z, b0.w);
            bp[2] = make_float2(b1.x, b1.y); bp[3] = make_float2(b1.z, b1.w);
            float a[8] = {a0.x, a0.y, a0.z, a0.w, a1.x, a1.y, a1.z, a1.w};
#pragma unroll
            for (int i = 0; i < 8; i++) {
                float2 ad = make_float2(a[i], a[i]);
#pragma unroll
                for (int q = 0; q < 4; q++)
                    acc[i][q] = ffma2(ad, bp[q], acc[i][q]);
            }
        }

        if (more) {
            const int nb = buf ^ 1;
            Asm[nb][ac + 0][ar] = av.x; Asm[nb][ac + 1][ar] = av.y;
            Asm[nb][ac + 2][ar] = av.z; Asm[nb][ac + 3][ar] = av.w;
            *(float4*)&Bsm[nb][br][bc] = bv;
        }
        __syncthreads();
    }

#pragma unroll
    for (int i = 0; i < 8; i++) {
        const int row = bm + ty * 8 + i;
#pragma unroll
        for (int g = 0; g < 2; g++) {
            const int col = bn + tx * 4 + g * 64;
            float4 v;
            v.x = acc[i][g * 2 + 0].x + bias[col + 0];
            v.y = acc[i][g * 2 + 0].y + bias[col + 1];
            v.z = acc[i][g * 2 + 1].x + bias[col + 2];
            v.w = acc[i][g * 2 + 1].y + bias[col + 3];
            if (RELU) {
                v.x = fmaxf(v.x, 0.f); v.y = fmaxf(v.y, 0.f);
                v.z = fmaxf(v.z, 0.f); v.w = fmaxf(v.w, 0.f);
            }
            *(float4*)(C + (size_t)row * N + col) = v;
        }
    }
}

__global__ void __launch_bounds__(256, 2)
sgemm2_bias(const float* __restrict__ A, const float* __restrict__ B,
            const float* __restrict__ bias, float* __restrict__ C,
            int N, int K)
{
    __shared__ float As[2][8][128];
    __shared__ float Bs[2][8][128];
    gemm_body<false>(A, B, bias, C, N, K, blockIdx.y * 128, blockIdx.x * 128, As, Bs);
}

__global__ void __launch_bounds__(256, 2)
small_gemms(const float* __restrict__ x,
            const float* __restrict__ ws1, const float* __restrict__ bs1,
            const float* __restrict__ w1c, const float* __restrict__ b1c,
            float* __restrict__ hs, float* __restrict__ hc)
{
    __shared__ float As[2][8][128];
    __shared__ float Bs[2][8][128];
    const int bx = blockIdx.x;
    if (bx < 2)
        gemm_body<true>(x, ws1, bs1, hs, HID,  DIM, blockIdx.y * 128, bx * 128, As, Bs);
    else
        gemm_body<true>(x, w1c, b1c, hc, HIDC, DIM, blockIdx.y * 128, 0, As, Bs);
}

// ---------------- complexity -> sigmoid -> budget ---------------------------
__global__ void complexity_kernel(const float* __restrict__ hc,
                                  const float* __restrict__ w2c,
                                  const float* __restrict__ b2c,
                                  float* __restrict__ out_c,
                                  int* __restrict__ budget)
{
    int warp = (blockIdx.x * blockDim.x + threadIdx.x) >> 5;
    int lane = threadIdx.x & 31;
    if (warp >= NTOK) return;
    const float* h = hc + (size_t)warp * HIDC;
    float s = 0.f;
#pragma unroll
    for (int i = lane; i < HIDC; i += 32) s += h[i] * w2c[i];
#pragma unroll
    for (int o = 16; o; o >>= 1) s += __shfl_xor_sync(0xFFFFFFFFu, s, o);
    if (lane == 0) {
        float z = s + b2c[0];
        float c = 1.f / (1.f + expf(-z));
        out_c[warp] = c;
        float raw = 100.f + 924.f * (c * c);
        raw = fminf(fmaxf(raw, 100.f), 1024.f);
        budget[warp] = (int)rintf(raw);
    }
}

// ---------------- top-k helpers ---------------------------------------------
__device__ __forceinline__ uint32_t f2mk(float f) {
    uint32_t u = __float_as_uint(f);
    return (u & 0x80000000u) ? ~u : (u | 0x80000000u);
}
__device__ __forceinline__ float mk2f(uint32_t mk) {
    uint32_t u = (mk & 0x80000000u) ? (mk ^ 0x80000000u) : ~mk;
    return __uint_as_float(u);
}

// ---------------- fused top-k: threshold select + counting sort -------------
// smem (dynamic ~52 KB): staging[2048] u64 | fin[2048] u64 | hist[4096] u32 |
//   chunksum[256] u32 | warp_aux[32] u32 | s_red[512] f32 | scal[4] u32
__global__ void __launch_bounds__(512, 2)
topk_kernel(const float* __restrict__ scores, const int* __restrict__ budget,
            float* __restrict__ out_idx, float* __restrict__ out_w,
            float* __restrict__ out_m)
{
    extern __shared__ char smem_raw[];
    unsigned long long* staging = (unsigned long long*)smem_raw;
    unsigned long long* fin     = staging + 2048;
    uint32_t* hist     = (uint32_t*)(fin + 2048);
    uint32_t* chunksum = hist + 4096;
    uint32_t* warp_aux = chunksum + 256;
    float*    s_red    = (float*)(warp_aux + 32);
    uint32_t* s_redu   = (uint32_t*)s_red;
    uint32_t* scal     = (uint32_t*)(s_red + 512);
    #define S_BSTAR scal[0]
    #define S_CNT   scal[1]

    const int t    = blockIdx.x;
    const int tid  = threadIdx.x;
    const int lane = tid & 31;
    const int wid  = tid >> 5;                 // 16 warps
    const float4* row4 = (const float4*)(scores + (size_t)t * POOL);

    uint32_t cnt = 0, bstar = 0;
    bool     use_sample = true;
    uint32_t target = 192;           // 2048 samples -> expected survivors ~1536

    for (int attempt = 0; attempt < 2; attempt++) {
        for (int i = tid; i < 4096; i += 512) hist[i] = 0;
        __syncthreads();

        // coarse (12-bit) histogram: contiguous sample (8KB) or exact full row
        if (use_sample) {
            float4 v = row4[tid];               // first 2048 elements
            atomicAdd(&hist[f2mk(v.x) >> 20], 1u);
            atomicAdd(&hist[f2mk(v.y) >> 20], 1u);
            atomicAdd(&hist[f2mk(v.z) >> 20], 1u);
            atomicAdd(&hist[f2mk(v.w) >> 20], 1u);
        } else {
#pragma unroll
            for (int s = 0; s < 8; s++) {
                float4 v = row4[tid + s * 512];
                atomicAdd(&hist[f2mk(v.x) >> 20], 1u);
                atomicAdd(&hist[f2mk(v.y) >> 20], 1u);
                atomicAdd(&hist[f2mk(v.z) >> 20], 1u);
                atomicAdd(&hist[f2mk(v.w) >> 20], 1u);
            }
        }
        __syncthreads();

        // suffix scan over 256 chunk sums (warp shuffles, 3 barriers)
        {
            uint32_t v = 0;
            if (tid < 256) {
                uint32_t cs = 0;
#pragma unroll
                for (int b = tid * 16; b < tid * 16 + 16; b++) cs += hist[b];
                v = cs;
#pragma unroll
                for (int o = 1; o < 32; o <<= 1) {
                    uint32_t u = __shfl_down_sync(0xFFFFFFFFu, v, o);
                    if (lane + o < 32) v += u;
                }
                if (lane == 0) warp_aux[wid] = v;   // warp total
            }
            __syncthreads();
            if (tid < 8) {
                uint32_t w = warp_aux[tid];
                uint32_t incl = w;
#pragma unroll
                for (int o = 1; o < 8; o <<= 1) {
                    uint32_t u = __shfl_down_sync(0xFFu, incl, o);
                    if (tid + o < 8) incl += u;
                }
                warp_aux[8 + tid] = incl - w;       // sum of warps > tid
            }
            __syncthreads();
            if (tid < 256) chunksum[tid] = v + warp_aux[8 + wid];
            __syncthreads();
        }

        // crossing chunk -> threshold bin bstar
        if (tid < 256) {
            uint32_t Sc = chunksum[tid];
            uint32_t Sn = (tid < 255) ? chunksum[tid + 1] : 0;
            if (Sc >= target && Sn < target) {
                uint32_t cum = Sn;
                int b;
                for (b = tid * 16 + 15; b > tid * 16; b--) {
                    cum += hist[b];
                    if (cum >= target) break;
                }
                S_BSTAR = (uint32_t)b;
            }
        }
        __syncthreads();
        bstar = S_BSTAR;

        // clear hist for reuse as FINE histogram
        for (int i = tid; i < 4096; i += 512) hist[i] = 0;
        __syncthreads();

        // ---- pass A: count survivors per thread (no atomics) ----------------
        uint32_t c = 0;
#pragma unroll
        for (int h = 0; h < 2; h++) {
            float4 vv[4];
#pragma unroll
            for (int s = 0; s < 4; s++) vv[s] = row4[tid + (h * 4 + s) * 512];
#pragma unroll
            for (int s = 0; s < 4; s++) {
                c += ((f2mk(vv[s].x) >> 20) >= bstar);
                c += ((f2mk(vv[s].y) >> 20) >= bstar);
                c += ((f2mk(vv[s].z) >> 20) >= bstar);
                c += ((f2mk(vv[s].w) >> 20) >= bstar);
            }
        }
        // warp inclusive prefix
        uint32_t incl = c;
#pragma unroll
        for (int o = 1; o < 32; o <<= 1) {
            uint32_t u = __shfl_up_sync(0xFFFFFFFFu, incl, o);
            if (lane >= o) incl += u;
        }
        const uint32_t excl = incl - c;
        if (lane == 31) warp_aux[wid] = incl;       // warp total
        __syncthreads();
        if (tid < 16) {
            uint32_t w = warp_aux[tid];
            uint32_t wi = w;
#pragma unroll
            for (int o = 1; o < 16; o <<= 1) {
                uint32_t u = __shfl_up_sync(0xFFFFu, wi, o);
                if (tid >= o) wi += u;
            }
            warp_aux[16 + tid] = wi - w;            // warp exclusive base
            if (tid == 15) S_CNT = wi;              // total survivors
        }
        __syncthreads();
        cnt = S_CNT;

        // ---- pass B: write survivors (deterministic slots) + fine hist ------
        uint32_t pos = warp_aux[16 + wid] + excl;
#pragma unroll
        for (int h = 0; h < 2; h++) {
            float4 vv[4];
#pragma unroll
            for (int s = 0; s < 4; s++) vv[s] = row4[tid + (h * 4 + s) * 512];
#pragma unroll
            for (int s = 0; s < 4; s++) {
                const int i4 = tid + (h * 4 + s) * 512;
                float vals[4] = {vv[s].x, vv[s].y, vv[s].z, vv[s].w};
#pragma unroll
                for (int e = 0; e < 4; e++) {
                    uint32_t mk = f2mk(vals[e]);
                    if ((mk >> 20) >= bstar) {
                        if (pos < 2048u) {
                            uint32_t idx = (uint32_t)(i4 * 4 + e);
                            staging[pos] = ((unsigned long long)mk << 32) |
                                           (unsigned long long)(0xFFFFFFFFu - idx);
                            uint32_t rel = mk - (bstar << 20);
                            uint32_t fb  = rel >> 13;
                            if (fb > 4095u) fb = 4095u;
                            atomicAdd(&hist[fb], 1u);
                        }
                        pos++;
                    }
                }
            }
        }
        __syncthreads();
        if (cnt >= (uint32_t)TOPK && cnt <= 2048u) break;
        use_sample = false;
        target = TOPK;
        __syncthreads();
    }
    if (cnt > 2048u) cnt = 2048u;

    // suffix scan fine hist -> per-bin scatter bases (desc order)
    {
        uint32_t v = 0;
        if (tid < 256) {
            uint32_t cs = 0;
#pragma unroll
            for (int b = tid * 16; b < tid * 16 + 16; b++) cs += hist[b];
            v = cs;
#pragma unroll
            for (int o = 1; o < 32; o <<= 1) {
                uint32_t u = __shfl_down_sync(0xFFFFFFFFu, v, o);
                if (lane + o < 32) v += u;
            }
            if (lane == 0) warp_aux[wid] = v;
        }
        __syncthreads();
        if (tid < 8) {
            uint32_t w = warp_aux[tid];
            uint32_t incl2 = w;
#pragma unroll
            for (int o = 1; o < 8; o <<= 1) {
                uint32_t u = __shfl_down_sync(0xFFu, incl2, o);
                if (tid + o < 8) incl2 += u;
            }
            warp_aux[8 + tid] = incl2 - w;
        }
        __syncthreads();
        if (tid < 256) chunksum[tid] = v + warp_aux[8 + wid];
        __syncthreads();
    }
    if (tid < 256) {
        uint32_t acc = (tid < 255) ? chunksum[tid + 1] : 0;
        for (int b = tid * 16 + 15; b >= tid * 16; b--) {
            uint32_t c2 = hist[b];
            hist[b] = acc;          // base for bin b = count in bins > b
            acc += c2;
        }
    }
    __syncthreads();

    // end = min{ base[fb] : base >= 1024 }  (prefix that contains the top-1024)
    {
        uint32_t lmin = cnt;
#pragma unroll
        for (int s = 0; s < 8; s++) {
            uint32_t b = hist[tid + s * 512];
            if (b >= (uint32_t)TOPK && b < lmin) lmin = b;
        }
        s_redu[tid] = lmin;
        __syncthreads();
        for (int o = 256; o; o >>= 1) {
            if (tid < o) {
                uint32_t a = s_redu[tid], b = s_redu[tid + o];
                s_redu[tid] = (b < a) ? b : a;
            }
            __syncthreads();
        }
    }
    const int end = (int)s_redu[0];
    __syncthreads();

    // scatter only bins intersecting [0, end)
    for (int i = tid; i < (int)cnt; i += 512) {
        unsigned long long k = staging[i];
        uint32_t mk  = (uint32_t)(k >> 32);
        uint32_t rel = mk - (bstar << 20);
        uint32_t fb  = rel >> 13;
        if (fb > 4095u) fb = 4095u;
        if (hist[fb] < (uint32_t)end) {
            uint32_t p = atomicAdd(&hist[fb], 1u);
            fin[p] = k;
        }
    }
    __syncthreads();

    // odd-even transposition over [0, end) until sorted
    while (true) {
        int moved = 0;
#pragma unroll
        for (int r = 0; r < 2; r++) {
            int i = tid + r * 512;
            int p = 2 * i;
            if (p + 1 < end) {
                unsigned long long a = fin[p], b = fin[p + 1];
                if (a < b) { fin[p] = b; fin[p + 1] = a; moved = 1; }
            }
        }
        __syncthreads();
#pragma unroll
        for (int r = 0; r < 2; r++) {
            int i = tid + r * 512;
            int p = 2 * i + 1;
            if (p + 1 < end) {
                unsigned long long a = fin[p], b = fin[p + 1];
                if (a < b) { fin[p] = b; fin[p + 1] = a; moved = 1; }
            }
        }
        if (!__syncthreads_or(moved)) break;
    }

    // softmax over sorted top-1024 + budget mask (tree reduce: bit-stable)
    const float vmax = mk2f((uint32_t)(fin[0] >> 32));
    unsigned long long p0 = fin[tid];
    unsigned long long p1 = fin[tid + 512];
    float e0 = expf(mk2f((uint32_t)(p0 >> 32)) - vmax);
    float e1 = expf(mk2f((uint32_t)(p1 >> 32)) - vmax);
    s_red[tid] = e0 + e1;
    __syncthreads();
    for (int o = 256; o; o >>= 1) {
        if (tid < o) s_red[tid] += s_red[tid + o];
        __syncthreads();
    }
    const float inv = 1.f / s_red[0];

    const int bud = budget[t];
    const size_t base = (size_t)t * TOPK;
    {
        uint32_t idx0 = 0xFFFFFFFFu - (uint32_t)(p0 & 0xFFFFFFFFull);
        float m0 = (tid < bud) ? 1.f : 0.f;
        out_idx[base + tid] = (float)idx0;
        out_w[base + tid]   = e0 * inv * m0;
        out_m[base + tid]   = m0;
        uint32_t idx1 = 0xFFFFFFFFu - (uint32_t)(p1 & 0xFFFFFFFFull);
        int jj = tid + 512;
        float m1 = (jj < bud) ? 1.f : 0.f;
        out_idx[base + jj] = (float)idx1;
        out_w[base + jj]   = e1 * inv * m1;
        out_m[base + jj]   = m1;
    }
    #undef S_BSTAR
    #undef S_CNT
}

// ---------------- launch -----------------------------------------------------
extern "C" void kernel_launch(void* const* d_in, const int* in_sizes, int n_in,
                              void* d_out, int out_size)
{
    const float* x   = (const float*)d_in[0];
    const float* w1c = (const float*)d_in[1];
    const float* b1c = (const float*)d_in[2];
    const float* w2c = (const float*)d_in[3];
    const float* b2c = (const float*)d_in[4];
    const float* ws1 = (const float*)d_in[5];
    const float* bs1 = (const float*)d_in[6];
    const float* ws2 = (const float*)d_in[7];
    const float* bs2 = (const float*)d_in[8];

    float* out     = (float*)d_out;
    float* out_idx = out;
    float* out_w   = out + (size_t)NTOK * TOPK;
    float* out_m   = out + 2 * (size_t)NTOK * TOPK;
    float* out_c   = out + 3 * (size_t)NTOK * TOPK;

    float *hs_p, *hc_p, *sc_p;
    int *bud_p;
    cudaGetSymbolAddress((void**)&hs_p,  g_hs);
    cudaGetSymbolAddress((void**)&hc_p,  g_hc);
    cudaGetSymbolAddress((void**)&sc_p,  g_scores);
    cudaGetSymbolAddress((void**)&bud_p, g_budget);

    const int TOPK_SMEM = 53248;   // 52 KB dynamic
    static bool attr_set = false;
    if (!attr_set) {
        cudaFuncSetAttribute(topk_kernel,
                             cudaFuncAttributeMaxDynamicSharedMemorySize, TOPK_SMEM);
        attr_set = true;
    }

    small_gemms<<<dim3(3, NTOK / 128), 256>>>(x, ws1, bs1, w1c, b1c, hs_p, hc_p);
    complexity_kernel<<<NTOK / 8, 256>>>(hc_p, w2c, b2c, out_c, bud_p);
    sgemm2_bias<<<dim3(POOL / 128, NTOK / 128), 256>>>(hs_p, ws2, bs2, sc_p, POOL, HID);
    topk_kernel<<<NTOK, 512, TOPK_SMEM>>>(sc_p, bud_p, out_idx, out_w, out_m);
}